// round 14
// baseline (speedup 1.0000x reference)
#include <cuda_runtime.h>
#include <cuda_fp16.h>
#include <math.h>
#include <stdint.h>

#define Bb_ 4
#define S_ 1024
#define D_ 1024
#define H_ 16
#define HD_ 64
#define R_ 128
#define NREL 257
#define NRELP 384
#define BS_ (Bb_*S_)   // 4096
#define EPSLN 1e-5f

// -------- device scratch --------
__device__ __half g_h16[BS_*D_];
__device__ __half g_qkv16[(size_t)3*BS_*D_];
__device__ __half g_o16[BS_*D_];
__device__ __half g_ff16[(size_t)BS_*4*D_];
__device__ __half g_rel16[NRELP*HD_];
__device__ float  g_zerob[NRELP];
__device__ __half g_p16[(size_t)BS_*H_*NRELP];    // fp16 P, stride 384
__device__ float  g_x2[BS_*D_];
__device__ __half g_wqkvT[(size_t)3*D_*D_];
__device__ float  g_bqkv[3*D_];
__device__ __half g_woT[D_*D_];
__device__ __half g_w1T[(size_t)D_*4*D_];
__device__ __half g_w2T[(size_t)4*D_*D_];

// ---------------- helpers ----------------
__device__ __forceinline__ float warp_sum(float v){
  #pragma unroll
  for (int o=16;o>0;o>>=1) v += __shfl_xor_sync(0xffffffffu, v, o);
  return v;
}
__device__ __forceinline__ void mma_f16(float* d, const uint32_t* a, const uint32_t* b){
  asm volatile("mma.sync.aligned.m16n8k16.row.col.f32.f16.f16.f32 "
    "{%0,%1,%2,%3}, {%4,%5,%6,%7}, {%8,%9}, {%0,%1,%2,%3};"
    : "+f"(d[0]),"+f"(d[1]),"+f"(d[2]),"+f"(d[3])
    : "r"(a[0]),"r"(a[1]),"r"(a[2]),"r"(a[3]), "r"(b[0]),"r"(b[1]));
}
__device__ __forceinline__ void ldsm4(uint32_t& r0, uint32_t& r1, uint32_t& r2, uint32_t& r3,
                                      uint32_t addr){
  asm volatile("ldmatrix.sync.aligned.m8n8.x4.shared.b16 {%0,%1,%2,%3}, [%4];"
    : "=r"(r0),"=r"(r1),"=r"(r2),"=r"(r3) : "r"(addr));
}
__device__ __forceinline__ void ldsm4t(uint32_t& r0, uint32_t& r1, uint32_t& r2, uint32_t& r3,
                                       uint32_t addr){
  asm volatile("ldmatrix.sync.aligned.m8n8.x4.trans.shared.b16 {%0,%1,%2,%3}, [%4];"
    : "=r"(r0),"=r"(r1),"=r"(r2),"=r"(r3) : "r"(addr));
}
__device__ __forceinline__ void cp16(uint32_t dst, const void* src){
  asm volatile("cp.async.cg.shared.global [%0], [%1], 16;" :: "r"(dst), "l"(src));
}
#define CP_COMMIT() asm volatile("cp.async.commit_group;" ::: "memory")
#define CP_WAIT1()  asm volatile("cp.async.wait_group 1;" ::: "memory")
#define CP_WAIT0()  asm volatile("cp.async.wait_group 0;" ::: "memory")
#define CP_WAIT2()  asm volatile("cp.async.wait_group 2;" ::: "memory")

#define EPI_BIAS        0
#define EPI_BIAS_RESID  1
#define EPI_BIAS_GELU   2
#define HST 40

// ---------------- fp16 mma GEMM: MTx128x32 tiles, 3-stage ------------------
// MT=128: 256 thr, 8 warps (4x2). MT=64: 128 thr, 4 warps (2x2).
// Warp tile is 32x64 in both. SPLIT=1: C base selected by n0>>10.
template<int EPI, int OUT16, int SPLIT, int MT>
__global__ void __launch_bounds__(256) hgemm(const __half* __restrict__ A,
                                             const __half* __restrict__ Bt,
                                             const float* __restrict__ bias,
                                             const float* __restrict__ resid,
                                             void* __restrict__ Cv,
                                             int M, int N, int K)
{
  constexpr int ABYT = MT*HST*2;
  constexpr int STG  = ABYT + 128*HST*2;
  extern __shared__ char sm[];
  const uint32_t smb = (uint32_t)__cvta_generic_to_shared(sm);
  const int tid = threadIdx.x;
  const int wid = tid >> 5, lane = tid & 31;
  const int warp_m = wid >> 1, warp_n = wid & 1;
  const int m0 = blockIdx.y*MT, n0 = blockIdx.x*128;
  const int lr = lane >> 2, lc = lane & 3;

  // A loader: 2 thr/row, 16 halves each (covers MT rows with 2*MT threads)
  const int grow = tid >> 1, gseg = (tid & 1)*16;
  const __half* Ag = A + (size_t)(m0 + grow)*K + gseg;
  const uint32_t a_s = smb + (grow*HST + gseg)*2;
  // B loader: MT=128 -> 2 thr/row 16 halves; MT=64 -> 1 thr/row 32 halves
  const int brow = (MT == 128) ? (tid >> 1) : tid;
  const int bseg = (MT == 128) ? (tid & 1)*16 : 0;
  const __half* Bg = Bt + (size_t)(n0 + brow)*K + bseg;
  const uint32_t b_s = smb + ABYT + (brow*HST + bseg)*2;

  const uint32_t a_lm = smb
      + (((warp_m*32 + (lane & 15))*HST) + ((lane >> 4)*8))*2;
  const uint32_t b_lm = smb + ABYT
      + (((warp_n*64 + (lane & 7) + ((lane >> 4)&1)*8)*HST) + (((lane >> 3)&1)*8))*2;

  float acc[2][8][4];
  #pragma unroll
  for (int i=0;i<2;i++)
    #pragma unroll
    for (int j=0;j<8;j++)
      #pragma unroll
      for (int t=0;t<4;t++) acc[i][j][t]=0.f;

  const int NC = K >> 5;
  auto load = [&](int c, int s){
    const __half* ga = Ag + c*32;
    const uint32_t da = a_s + s*STG;
    cp16(da,      ga);
    cp16(da + 16, ga + 8);
    const __half* gb = Bg + c*32;
    const uint32_t db = b_s + s*STG;
    if (MT == 128){
      cp16(db,      gb);
      cp16(db + 16, gb + 8);
    } else {
      cp16(db,      gb);      cp16(db + 16, gb + 8);
      cp16(db + 32, gb + 16); cp16(db + 48, gb + 24);
    }
  };

  load(0,0); CP_COMMIT();
  if (NC > 1) load(1,1);
  CP_COMMIT();

  for (int c = 0; c < NC; c++){
    const int s = c - (c/3)*3;
    if (c + 1 < NC) CP_WAIT1(); else CP_WAIT0();
    __syncthreads();
    const uint32_t abase = a_lm + s*STG;
    const uint32_t bbase = b_lm + s*STG;
    #pragma unroll
    for (int ks=0; ks<2; ks++){
      uint32_t a[2][4], b[8][2];
      #pragma unroll
      for (int mf=0; mf<2; mf++)
        ldsm4(a[mf][0], a[mf][1], a[mf][2], a[mf][3],
              abase + (mf*16*HST + ks*16)*2);
      #pragma unroll
      for (int np=0; np<4; np++){
        uint32_t r0,r1,r2,r3;
        ldsm4(r0,r1,r2,r3, bbase + (np*16*HST + ks*16)*2);
        b[np*2+0][0]=r0; b[np*2+0][1]=r1;
        b[np*2+1][0]=r2; b[np*2+1][1]=r3;
      }
      #pragma unroll
      for (int mf=0; mf<2; mf++)
        #pragma unroll
        for (int nf=0; nf<8; nf++)
          mma_f16(acc[mf][nf], a[mf], b[nf]);
    }
    if (c + 2 < NC) load(c+2, (c+2) - ((c+2)/3)*3);
    CP_COMMIT();
    __syncthreads();
  }

  __half* Cb16 = nullptr;
  if (SPLIT) Cb16 = (__half*)Cv + (size_t)(n0 >> 10)*BS_*D_;
  #pragma unroll
  for (int mf=0; mf<2; mf++){
    #pragma unroll
    for (int half=0; half<2; half++){
      const int row = m0 + warp_m*32 + mf*16 + lr + half*8;
      const float* rrow = (EPI == EPI_BIAS_RESID) ? (resid + (size_t)row*N) : nullptr;
      #pragma unroll
      for (int nf=0; nf<8; nf++){
        const int col = n0 + warp_n*64 + nf*8 + 2*lc;
        float v0 = acc[mf][nf][half*2 + 0] + bias[col];
        float v1 = acc[mf][nf][half*2 + 1] + bias[col+1];
        if (EPI == EPI_BIAS_RESID){ v0 += rrow[col]; v1 += rrow[col+1]; }
        if (EPI == EPI_BIAS_GELU){
          v0 = 0.5f*v0*(1.0f + erff(v0*0.70710678118654752f));
          v1 = 0.5f*v1*(1.0f + erff(v1*0.70710678118654752f));
        }
        if (SPLIT){
          __half2 hv = __floats2half2_rn(v0, v1);
          *(__half2*)(Cb16 + (size_t)row*D_ + (col & 1023)) = hv;
        } else if (OUT16){
          __half2 hv = __floats2half2_rn(v0, v1);
          *(__half2*)((__half*)Cv + (size_t)row*N + col) = hv;
        } else {
          *(float2*)((float*)Cv + (size_t)row*N + col) = make_float2(v0, v1);
        }
      }
    }
  }
}

#define GEMM_SMEM64  (3*((64 +128)*HST*2))   // 46080
#define GEMM_SMEM128 (3*((128+128)*HST*2))   // 61440

// ---------------- fused flash attention: 128 thr, 64-q tile, clamp-aware ---
#define FST 72
#define QTILE_B (64*FST*2)        // 9216
#define KVSTG   (2*QTILE_B)       // 18432
#define FLASH_SMEM (QTILE_B + 3*KVSTG)  // 64512
#define NKT (S_/64)               // 16
__global__ void __launch_bounds__(128) flash_attn(const __half* __restrict__ Q,
                                                  const __half* __restrict__ Km,
                                                  const __half* __restrict__ Vm,
                                                  const __half* __restrict__ P,
                                                  __half* __restrict__ O)
{
  extern __shared__ char sm[];
  const int bh = blockIdx.y, b = bh >> 4, h = bh & 15;
  const int q0 = blockIdx.x*64;
  const int tid = threadIdx.x, wid = tid >> 5, lane = tid & 31;
  const int lr = lane >> 2, lc = lane & 3;
  const size_t base = (size_t)b*S_*D_ + h*HD_;
  const uint32_t smb = (uint32_t)__cvta_generic_to_shared(sm);

  const int grow = tid >> 1, gseg = (tid & 1)*32;
  {
    const __half* qg = Q + base + (size_t)(q0 + grow)*D_ + gseg;
    uint32_t dst = smb + (grow*FST + gseg)*2;
    cp16(dst,    qg);     cp16(dst+16, qg+8);
    cp16(dst+32, qg+16);  cp16(dst+48, qg+24);
  }
  CP_COMMIT();
  auto load_kv = [&](int c, int s){
    const __half* kg = Km + base + (size_t)(c*64 + grow)*D_ + gseg;
    const __half* vg = Vm + base + (size_t)(c*64 + grow)*D_ + gseg;
    uint32_t kd = smb + QTILE_B + s*KVSTG + (grow*FST + gseg)*2;
    uint32_t vd = kd + QTILE_B;
    cp16(kd,    kg);     cp16(kd+16, kg+8);
    cp16(kd+32, kg+16);  cp16(kd+48, kg+24);
    cp16(vd,    vg);     cp16(vd+16, vg+8);
    cp16(vd+32, vg+16);  cp16(vd+48, vg+24);
  };
  load_kv(0,0); CP_COMMIT();
  load_kv(1,1); CP_COMMIT();

  CP_WAIT2();
  __syncthreads();

  uint32_t a_q[4][4];
  {
    const uint32_t a_lm = smb + (((wid*16 + (lane & 15))*FST) + ((lane >> 4)*8))*2;
    const __half2 sc8 = __half2half2(__float2half(0.125f));
    #pragma unroll
    for (int ks=0; ks<4; ks++){
      ldsm4(a_q[ks][0], a_q[ks][1], a_q[ks][2], a_q[ks][3], a_lm + (ks*16)*2);
      #pragma unroll
      for (int r=0;r<4;r++){
        __half2 hv = *reinterpret_cast<__half2*>(&a_q[ks][r]);
        hv = __hmul2(hv, sc8);
        a_q[ks][r] = *reinterpret_cast<uint32_t*>(&hv);
      }
    }
  }

  const int qrow0 = q0 + wid*16 + lr;
  const __half* prow0 = P + ((size_t)(b*S_ + qrow0)*H_ + h)*NRELP + R_;
  const __half* prow1 = prow0 + (size_t)8*H_*NRELP;

  float m0 = -1e30f, m1 = -1e30f, l0 = 0.f, l1 = 0.f;
  float acc_o[8][4];
  #pragma unroll
  for (int j=0;j<8;j++)
    #pragma unroll
    for (int t=0;t<4;t++) acc_o[j][t] = 0.f;

  for (int kt = 0; kt < NKT; kt++){
    const int s = kt - (kt/3)*3;
    CP_WAIT1();
    __syncthreads();
    const uint32_t kbase = smb + QTILE_B + s*KVSTG;
    const uint32_t vbase = kbase + QTILE_B;

    float accs[8][4];
    #pragma unroll
    for (int j=0;j<8;j++)
      #pragma unroll
      for (int t=0;t<4;t++) accs[j][t] = 0.f;

    const uint32_t bk_lm = kbase
        + ((((lane & 7) + ((lane >> 4)&1)*8)*FST) + (((lane >> 3)&1)*8))*2;
    #pragma unroll
    for (int ks=0; ks<4; ks++){
      uint32_t bfr[8][2];
      #pragma unroll
      for (int np=0; np<4; np++){
        uint32_t r0,r1,r2,r3;
        ldsm4(r0,r1,r2,r3, bk_lm + (np*16*FST + ks*16)*2);
        bfr[np*2+0][0]=r0; bfr[np*2+0][1]=r1;
        bfr[np*2+1][0]=r2; bfr[np*2+1][1]=r3;
      }
      #pragma unroll
      for (int nf=0; nf<8; nf++)
        mma_f16(accs[nf], a_q[ks], bfr[nf]);
    }

    const int dmin = kt*64 - (q0 + 63);
    const int dmax = kt*64 + 63 - q0;
    if (dmin >= R_ || dmax <= -R_){
      const int off = (dmin >= R_) ? R_ : -R_;
      const float b0 = __half2float(__ldg(prow0 + off));
      const float b1 = __half2float(__ldg(prow1 + off));
      #pragma unroll
      for (int nf=0; nf<8; nf++){
        accs[nf][0] += b0; accs[nf][1] += b0;
        accs[nf][2] += b1; accs[nf][3] += b1;
      }
    } else {
      const int cq0 = kt*64 + 2*lc - qrow0;
      #pragma unroll
      for (int nf=0; nf<8; nf++){
        int c0 = cq0 + nf*8;
        int i00 = c0;     i00 = i00 < -R_ ? -R_ : (i00 > R_ ? R_ : i00);
        int i01 = c0 + 1; i01 = i01 < -R_ ? -R_ : (i01 > R_ ? R_ : i01);
        int i10 = c0 - 8; i10 = i10 < -R_ ? -R_ : (i10 > R_ ? R_ : i10);
        int i11 = c0 - 7; i11 = i11 < -R_ ? -R_ : (i11 > R_ ? R_ : i11);
        accs[nf][0] += __half2float(__ldg(prow0 + i00));
        accs[nf][1] += __half2float(__ldg(prow0 + i01));
        accs[nf][2] += __half2float(__ldg(prow1 + i10));
        accs[nf][3] += __half2float(__ldg(prow1 + i11));
      }
    }

    float mx0 = -1e30f, mx1 = -1e30f;
    #pragma unroll
    for (int nf=0; nf<8; nf++){
      mx0 = fmaxf(mx0, fmaxf(accs[nf][0], accs[nf][1]));
      mx1 = fmaxf(mx1, fmaxf(accs[nf][2], accs[nf][3]));
    }
    mx0 = fmaxf(mx0, __shfl_xor_sync(0xffffffffu, mx0, 1));
    mx0 = fmaxf(mx0, __shfl_xor_sync(0xffffffffu, mx0, 2));
    mx1 = fmaxf(mx1, __shfl_xor_sync(0xffffffffu, mx1, 1));
    mx1 = fmaxf(mx1, __shfl_xor_sync(0xffffffffu, mx1, 2));
    const float mn0 = fmaxf(m0, mx0), mn1 = fmaxf(m1, mx1);
    const float cr0 = __expf(m0 - mn0), cr1 = __expf(m1 - mn1);
    m0 = mn0; m1 = mn1;

    float rs0 = 0.f, rs1 = 0.f;
    uint32_t a_p[4][4];
    #pragma unroll
    for (int kf=0; kf<4; kf++){
      float p00 = __expf(accs[2*kf  ][0] - m0);
      float p01 = __expf(accs[2*kf  ][1] - m0);
      float p10 = __expf(accs[2*kf  ][2] - m1);
      float p11 = __expf(accs[2*kf  ][3] - m1);
      float q00 = __expf(accs[2*kf+1][0] - m0);
      float q01 = __expf(accs[2*kf+1][1] - m0);
      float q10 = __expf(accs[2*kf+1][2] - m1);
      float q11 = __expf(accs[2*kf+1][3] - m1);
      rs0 += p00 + p01 + q00 + q01;
      rs1 += p10 + p11 + q10 + q11;
      __half2 hv;
      hv = __floats2half2_rn(p00, p01); a_p[kf][0] = *reinterpret_cast<uint32_t*>(&hv);
      hv = __floats2half2_rn(p10, p11); a_p[kf][1] = *reinterpret_cast<uint32_t*>(&hv);
      hv = __floats2half2_rn(q00, q01); a_p[kf][2] = *reinterpret_cast<uint32_t*>(&hv);
      hv = __floats2half2_rn(q10, q11); a_p[kf][3] = *reinterpret_cast<uint32_t*>(&hv);
    }
    rs0 += __shfl_xor_sync(0xffffffffu, rs0, 1);
    rs0 += __shfl_xor_sync(0xffffffffu, rs0, 2);
    rs1 += __shfl_xor_sync(0xffffffffu, rs1, 1);
    rs1 += __shfl_xor_sync(0xffffffffu, rs1, 2);
    l0 = l0*cr0 + rs0;
    l1 = l1*cr1 + rs1;
    #pragma unroll
    for (int nf=0; nf<8; nf++){
      acc_o[nf][0] *= cr0; acc_o[nf][1] *= cr0;
      acc_o[nf][2] *= cr1; acc_o[nf][3] *= cr1;
    }

    const uint32_t bv_lm = vbase
        + ((((lane & 7) + ((lane >> 3)&1)*8)*FST) + (((lane >> 4)&1)*8))*2;
    #pragma unroll
    for (int kf=0; kf<4; kf++){
      uint32_t bfr[8][2];
      #pragma unroll
      for (int np=0; np<4; np++){
        uint32_t r0,r1,r2,r3;
        ldsm4t(r0,r1,r2,r3, bv_lm + (kf*16*FST + np*16)*2);
        bfr[np*2+0][0]=r0; bfr[np*2+0][1]=r1;
        bfr[np*2+1][0]=r2; bfr[np*2+1][1]=r3;
      }
      #pragma unroll
      for (int nf=0; nf<8; nf++)
        mma_f16(acc_o[nf], a_p[kf], bfr[nf]);
    }

    if (kt + 2 < NKT) load_kv(kt+2, (kt+2) - ((kt+2)/3)*3);
    CP_COMMIT();
    __syncthreads();
  }

  const float inv0 = 1.f/l0, inv1 = 1.f/l1;
  __half* orow0 = O + base + (size_t)qrow0*D_;
  __half* orow1 = orow0 + 8*D_;
  #pragma unroll
  for (int nf=0; nf<8; nf++){
    const int col = nf*8 + 2*lc;
    *(__half2*)(orow0 + col) = __floats2half2_rn(acc_o[nf][0]*inv0, acc_o[nf][1]*inv0);
    *(__half2*)(orow1 + col) = __floats2half2_rn(acc_o[nf][2]*inv1, acc_o[nf][3]*inv1);
  }
}

// ---------------- fused weight transposes ----------------
__global__ void __launch_bounds__(256) transpose_all(const float* __restrict__ wq,
                                                     const float* __restrict__ wk,
                                                     const float* __restrict__ wv,
                                                     const float* __restrict__ wo,
                                                     const float* __restrict__ w1,
                                                     const float* __restrict__ w2,
                                                     __half* __restrict__ wqkvT,
                                                     __half* __restrict__ woT,
                                                     __half* __restrict__ w1T,
                                                     __half* __restrict__ w2T)
{
  __shared__ float t[32][33];
  const int tb = blockIdx.x;
  const float* W; __half* Wt; int Kd, Nd, lt;
  if      (tb <  1024){ W=wq; Wt=wqkvT;            Kd=D_;   Nd=D_;   lt=tb; }
  else if (tb <  2048){ W=wk; Wt=wqkvT +   D_*D_;  Kd=D_;   Nd=D_;   lt=tb-1024; }
  else if (tb <  3072){ W=wv; Wt=wqkvT + 2*D_*D_;  Kd=D_;   Nd=D_;   lt=tb-2048; }
  else if (tb <  4096){ W=wo; Wt=woT;              Kd=D_;   Nd=D_;   lt=tb-3072; }
  else if (tb <  8192){ W=w1; Wt=w1T;              Kd=D_;   Nd=4*D_; lt=tb-4096; }
  else                { W=w2; Wt=w2T;              Kd=4*D_; Nd=D_;   lt=tb-8192; }
  const int ntx = Nd >> 5;
  const int bx = lt % ntx, by = lt / ntx;
  const int tx = threadIdx.x & 31, ty = threadIdx.x >> 5;

  int n = bx*32 + tx;
  int k = by*32 + ty;
  #pragma unroll
  for (int i=0;i<32;i+=8)
    t[ty+i][tx] = W[(size_t)(k+i)*Nd + n];
  __syncthreads();
  int n2 = bx*32 + ty;
  int k2 = by*32 + tx;
  #pragma unroll
  for (int i=0;i<32;i+=8)
    Wt[(size_t)(n2+i)*Kd + k2] = __float2half_rn(t[tx][ty+i]);
}

// ---------------- bias concat ----------------
__global__ void bias_concat(const float* __restrict__ bq, const float* __restrict__ bk,
                            const float* __restrict__ bv, float* __restrict__ bqkv){
  int i = blockIdx.x*256 + threadIdx.x;
  if (i < D_)            bqkv[i] = bq[i];
  else if (i < 2*D_)     bqkv[i] = bk[i - D_];
  else if (i < 3*D_)     bqkv[i] = bv[i - 2*D_];
}

// ---------------- rel fp32 -> fp16, pre-scaled 0.125, zero-padded ---------
__global__ void rel_convert(const float* __restrict__ rel, __half* __restrict__ rel16){
  int i = blockIdx.x*256 + threadIdx.x;
  if (i < NRELP*HD_){
    int r = i >> 6;
    float v = (r < NREL) ? rel[i]*0.125f : 0.f;
    rel16[i] = __float2half_rn(v);
  }
}

// ---------------- LayerNorm: warp-per-row ----------------
__global__ void __launch_bounds__(256) ln_kernel_w(const float* __restrict__ x,
                                                   const float* __restrict__ g,
                                                   const float* __restrict__ bta,
                                                   __half* __restrict__ y)
{
  const int wid = threadIdx.x >> 5, lane = threadIdx.x & 31;
  const int row = blockIdx.x*8 + wid;
  const float* xr = x + (size_t)row*D_;
  float4 v[8];
  float s = 0.f, ss = 0.f;
  #pragma unroll
  for (int i=0;i<8;i++){
    v[i] = *(const float4*)(xr + (lane + i*32)*4);
    s  += v[i].x + v[i].y + v[i].z + v[i].w;
    ss += v[i].x*v[i].x + v[i].y*v[i].y + v[i].z*v[i].z + v[i].w*v[i].w;
  }
  s = warp_sum(s); ss = warp_sum(ss);
  const float mu = s*(1.f/(float)D_);
  const float rs = rsqrtf(ss*(1.f/(float)D_) - mu*mu + EPSLN);
  #pragma unroll
  for (int i=0;i<8;i++){
    const int c = (lane + i*32)*4;
    float4 gv = *(const float4*)(g   + c);
    float4 bv = *(const float4*)(bta + c);
    __half2 h0 = __floats2half2_rn((v[i].x-mu)*rs*gv.x + bv.x, (v[i].y-mu)*rs*gv.y + bv.y);
    __half2 h1 = __floats2half2_rn((v[i].z-mu)*rs*gv.z + bv.z, (v[i].w-mu)*rs*gv.w + bv.w);
    uint2 pk; pk.x = *(uint32_t*)&h0; pk.y = *(uint32_t*)&h1;
    *(uint2*)(y + (size_t)row*D_ + c) = pk;
  }
}

// ---------------- launcher ----------------
extern "C" void kernel_launch(void* const* d_in, const int* in_sizes, int n_in,
                              void* d_out, int out_size)
{
  const float* x    = (const float*)d_in[0];
  const float* wq   = (const float*)d_in[1];
  const float* bq   = (const float*)d_in[2];
  const float* wk   = (const float*)d_in[3];
  const float* bk   = (const float*)d_in[4];
  const float* wv   = (const float*)d_in[5];
  const float* bv   = (const float*)d_in[6];
  const float* wo   = (const float*)d_in[7];
  const float* bo   = (const float*)d_in[8];
  const float* rel  = (const float*)d_in[9];
  const float* ln1g = (const float*)d_in[10];
  const float* ln1b = (const float*)d_in[11];
  const float* ln2g = (const float*)d_in[12];
  const float* ln2b = (const float*)d_in[13];
  const float* w1   = (const float*)d_in[14];
  const float* b1   = (const float*)d_in[15];
  const float* w2   = (const float*)d_in[16];
  const float* b2   = (const float*)d_in[17];
  float* out = (float*)d_out;

  __half *h16_, *qkv16_, *o16_, *ff16_, *rel16_, *p16_;
  __half *wqkvT_, *woT_, *w1T_, *w2T_;
  float *x2_, *bqkv_, *zerob_;
  cudaGetSymbolAddress((void**)&h16_,  g_h16);
  cudaGetSymbolAddress((void**)&qkv16_,g_qkv16);
  cudaGetSymbolAddress((void**)&o16_,  g_o16);
  cudaGetSymbolAddress((void**)&ff16_, g_ff16);
  cudaGetSymbolAddress((void**)&rel16_,g_rel16);
  cudaGetSymbolAddress((void**)&p16_,  g_p16);
  cudaGetSymbolAddress((void**)&x2_,   g_x2);
  cudaGetSymbolAddress((void**)&wqkvT_,g_wqkvT);
  cudaGetSymbolAddress((void**)&bqkv_, g_bqkv);
  cudaGetSymbolAddress((void**)&zerob_,g_zerob);
  cudaGetSymbolAddress((void**)&woT_,  g_woT);
  cudaGetSymbolAddress((void**)&w1T_,  g_w1T);
  cudaGetSymbolAddress((void**)&w2T_,  g_w2T);

  __half* q16_ = qkv16_;
  __half* k16_ = qkv16_ + (size_t)BS_*D_;
  __half* v16_ = qkv16_ + (size_t)2*BS_*D_;

  static bool init_done = false;
  if (!init_done){
    cudaFuncSetAttribute(hgemm<EPI_BIAS,1,1,64>,        cudaFuncAttributeMaxDynamicSharedMemorySize, GEMM_SMEM64);
    cudaFuncSetAttribute(hgemm<EPI_BIAS_RESID,0,0,64>,  cudaFuncAttributeMaxDynamicSharedMemorySize, GEMM_SMEM64);
    cudaFuncSetAttribute(hgemm<EPI_BIAS_GELU,1,0,64>,   cudaFuncAttributeMaxDynamicSharedMemorySize, GEMM_SMEM64);
    cudaFuncSetAttribute(hgemm<EPI_BIAS,1,0,128>,       cudaFuncAttributeMaxDynamicSharedMemorySize, GEMM_SMEM128);
    cudaFuncSetAttribute(flash_attn, cudaFuncAttributeMaxDynamicSharedMemorySize, FLASH_SMEM);
    init_done = true;
  }

  // 0. preprocessing
  transpose_all<<<12288, 256>>>(wq, wk, wv, wo, w1, w2, wqkvT_, woT_, w1T_, w2T_);
  bias_concat<<<12, 256>>>(bq, bk, bv, bqkv_);
  rel_convert<<<(NRELP*HD_ + 255)/256, 256>>>(rel, rel16_);

  // 1. LN1 -> fp16
  ln_kernel_w<<<BS_/8, 256>>>(x, ln1g, ln1b, h16_);
  // 2. merged QKV projection (64-row tiles, 128 thr)
  hgemm<EPI_BIAS,1,1,64><<<dim3(24,64), 128, GEMM_SMEM64>>>(h16_, wqkvT_, bqkv_, nullptr, qkv16_, BS_, 3*D_, D_);
  // 3. rel projection as GEMM -> fp16 P (prologue-heavy: 128-row tiles, 256 thr)
  hgemm<EPI_BIAS,1,0,128><<<dim3(3,512), 256, GEMM_SMEM128>>>(q16_, rel16_, zerob_, nullptr, p16_, BS_*H_, NRELP, HD_);
  // 4. fused flash attention -> o16
  flash_attn<<<dim3(16, Bb_*H_), 128, FLASH_SMEM>>>(q16_, k16_, v16_, p16_, o16_);
  // 5. output projection + residual (fp32 out)
  hgemm<EPI_BIAS_RESID,0,0,64><<<dim3(8,64), 128, GEMM_SMEM64>>>(o16_, woT_, bo, x, x2_, BS_, D_, D_);
  // 6. LN2 -> fp16
  ln_kernel_w<<<BS_/8, 256>>>(x2_, ln2g, ln2b, h16_);
  // 7. FFN1 + exact GELU (fp16 out)
  hgemm<EPI_BIAS_GELU,1,0,64><<<dim3(32,64), 128, GEMM_SMEM64>>>(h16_, w1T_, b1, nullptr, ff16_, BS_, 4*D_, D_);
  // 8. FFN2 + residual -> out (fp32)
  hgemm<EPI_BIAS_RESID,0,0,64><<<dim3(8,64), 128, GEMM_SMEM64>>>(ff16_, w2T_, b2, x2_, out, BS_, D_, 4*D_);
}

// round 15
// speedup vs baseline: 1.3306x; 1.3306x over previous
#include <cuda_runtime.h>
#include <cuda_fp16.h>
#include <math.h>
#include <stdint.h>

#define Bb_ 4
#define S_ 1024
#define D_ 1024
#define H_ 16
#define HD_ 64
#define R_ 128
#define NREL 257
#define NRELP 384
#define BS_ (Bb_*S_)   // 4096
#define EPSLN 1e-5f

// -------- device scratch --------
__device__ __half g_h16[BS_*D_];
__device__ __half g_qkv16[(size_t)3*BS_*D_];
__device__ __half g_o16[BS_*D_];
__device__ __half g_ff16[(size_t)BS_*4*D_];
__device__ __half g_rel16[NRELP*HD_];
__device__ float  g_zerob[NRELP];
__device__ __half g_p16[(size_t)BS_*H_*NRELP];    // fp16 P, stride 384
__device__ float  g_x2[BS_*D_];
__device__ __half g_wqkvT[(size_t)3*D_*D_];
__device__ float  g_bqkv[3*D_];
__device__ __half g_woT[D_*D_];
__device__ __half g_w1T[(size_t)D_*4*D_];
__device__ __half g_w2T[(size_t)4*D_*D_];

// ---------------- helpers ----------------
__device__ __forceinline__ float warp_sum(float v){
  #pragma unroll
  for (int o=16;o>0;o>>=1) v += __shfl_xor_sync(0xffffffffu, v, o);
  return v;
}
__device__ __forceinline__ void mma_f16(float* d, const uint32_t* a, const uint32_t* b){
  asm volatile("mma.sync.aligned.m16n8k16.row.col.f32.f16.f16.f32 "
    "{%0,%1,%2,%3}, {%4,%5,%6,%7}, {%8,%9}, {%0,%1,%2,%3};"
    : "+f"(d[0]),"+f"(d[1]),"+f"(d[2]),"+f"(d[3])
    : "r"(a[0]),"r"(a[1]),"r"(a[2]),"r"(a[3]), "r"(b[0]),"r"(b[1]));
}
__device__ __forceinline__ void ldsm4(uint32_t& r0, uint32_t& r1, uint32_t& r2, uint32_t& r3,
                                      uint32_t addr){
  asm volatile("ldmatrix.sync.aligned.m8n8.x4.shared.b16 {%0,%1,%2,%3}, [%4];"
    : "=r"(r0),"=r"(r1),"=r"(r2),"=r"(r3) : "r"(addr));
}
__device__ __forceinline__ void ldsm4t(uint32_t& r0, uint32_t& r1, uint32_t& r2, uint32_t& r3,
                                       uint32_t addr){
  asm volatile("ldmatrix.sync.aligned.m8n8.x4.trans.shared.b16 {%0,%1,%2,%3}, [%4];"
    : "=r"(r0),"=r"(r1),"=r"(r2),"=r"(r3) : "r"(addr));
}
__device__ __forceinline__ void cp16(uint32_t dst, const void* src){
  asm volatile("cp.async.cg.shared.global [%0], [%1], 16;" :: "r"(dst), "l"(src));
}
#define CP_COMMIT() asm volatile("cp.async.commit_group;" ::: "memory")
#define CP_WAIT1()  asm volatile("cp.async.wait_group 1;" ::: "memory")
#define CP_WAIT0()  asm volatile("cp.async.wait_group 0;" ::: "memory")
#define CP_WAIT2()  asm volatile("cp.async.wait_group 2;" ::: "memory")

#define EPI_BIAS        0
#define EPI_BIAS_RESID  1
#define EPI_BIAS_GELU   2
#define HST 40
#define HBYTES (128*HST*2)          // 10240
#define GEMM_SMEM (6*HBYTES)        // 61440 -> 2 CTAs/SM

// ---------------- fp16 mma GEMM: 128x128x32, 8 warps, 3-stage -------------
template<int EPI, int OUT16, int SPLIT>
__global__ void __launch_bounds__(256) hgemm(const __half* __restrict__ A,
                                             const __half* __restrict__ Bt,
                                             const float* __restrict__ bias,
                                             const float* __restrict__ resid,
                                             void* __restrict__ Cv,
                                             int M, int N, int K)
{
  extern __shared__ char sm[];
  __half* Asm = (__half*)sm;
  __half* Bsm = (__half*)(sm + 3*HBYTES);
  const int tid = threadIdx.x;
  const int wid = tid >> 5, lane = tid & 31;
  const int warp_m = wid >> 1, warp_n = wid & 1;
  const int m0 = blockIdx.y*128, n0 = blockIdx.x*128;
  const int lr = lane >> 2, lc = lane & 3;
  const int grow = tid >> 1, gseg = (tid & 1)*16;

  const __half* Ag = A  + (size_t)(m0 + grow)*K + gseg;
  const __half* Bg = Bt + (size_t)(n0 + grow)*K + gseg;
  const uint32_t a_s = (uint32_t)__cvta_generic_to_shared(Asm) + (grow*HST + gseg)*2;
  const uint32_t b_s = (uint32_t)__cvta_generic_to_shared(Bsm) + (grow*HST + gseg)*2;

  const uint32_t a_lm = (uint32_t)__cvta_generic_to_shared(Asm)
      + (((warp_m*32 + (lane & 15))*HST) + ((lane >> 4)*8))*2;
  const uint32_t b_lm = (uint32_t)__cvta_generic_to_shared(Bsm)
      + (((warp_n*64 + (lane & 7) + ((lane >> 4)&1)*8)*HST) + (((lane >> 3)&1)*8))*2;

  float acc[2][8][4];
  #pragma unroll
  for (int i=0;i<2;i++)
    #pragma unroll
    for (int j=0;j<8;j++)
      #pragma unroll
      for (int t=0;t<4;t++) acc[i][j][t]=0.f;

  const int NC = K >> 5;
  auto load = [&](int c, int s){
    const __half* ga = Ag + c*32;
    const __half* gb = Bg + c*32;
    const uint32_t da = a_s + s*HBYTES;
    const uint32_t db = b_s + s*HBYTES;
    cp16(da,      ga);
    cp16(da + 16, ga + 8);
    cp16(db,      gb);
    cp16(db + 16, gb + 8);
  };

  load(0,0); CP_COMMIT();
  if (NC > 1) load(1,1);
  CP_COMMIT();

  for (int c = 0; c < NC; c++){
    const int s = c - (c/3)*3;
    if (c + 1 < NC) CP_WAIT1(); else CP_WAIT0();
    __syncthreads();
    const uint32_t abase = a_lm + s*HBYTES;
    const uint32_t bbase = b_lm + s*HBYTES;
    #pragma unroll
    for (int ks=0; ks<2; ks++){
      uint32_t a[2][4], b[8][2];
      #pragma unroll
      for (int mf=0; mf<2; mf++)
        ldsm4(a[mf][0], a[mf][1], a[mf][2], a[mf][3],
              abase + (mf*16*HST + ks*16)*2);
      #pragma unroll
      for (int np=0; np<4; np++){
        uint32_t r0,r1,r2,r3;
        ldsm4(r0,r1,r2,r3, bbase + (np*16*HST + ks*16)*2);
        b[np*2+0][0]=r0; b[np*2+0][1]=r1;
        b[np*2+1][0]=r2; b[np*2+1][1]=r3;
      }
      #pragma unroll
      for (int mf=0; mf<2; mf++)
        #pragma unroll
        for (int nf=0; nf<8; nf++)
          mma_f16(acc[mf][nf], a[mf], b[nf]);
    }
    if (c + 2 < NC) load(c+2, (c+2) - ((c+2)/3)*3);
    CP_COMMIT();
    __syncthreads();
  }

  __half* Cb16 = nullptr;
  if (SPLIT) Cb16 = (__half*)Cv + (size_t)(n0 >> 10)*BS_*D_;
  #pragma unroll
  for (int mf=0; mf<2; mf++){
    #pragma unroll
    for (int half=0; half<2; half++){
      const int row = m0 + warp_m*32 + mf*16 + lr + half*8;
      const float* rrow = (EPI == EPI_BIAS_RESID) ? (resid + (size_t)row*N) : nullptr;
      #pragma unroll
      for (int nf=0; nf<8; nf++){
        const int col = n0 + warp_n*64 + nf*8 + 2*lc;
        float v0 = acc[mf][nf][half*2 + 0] + bias[col];
        float v1 = acc[mf][nf][half*2 + 1] + bias[col+1];
        if (EPI == EPI_BIAS_RESID){ v0 += rrow[col]; v1 += rrow[col+1]; }
        if (EPI == EPI_BIAS_GELU){
          v0 = 0.5f*v0*(1.0f + erff(v0*0.70710678118654752f));
          v1 = 0.5f*v1*(1.0f + erff(v1*0.70710678118654752f));
        }
        if (SPLIT){
          __half2 hv = __floats2half2_rn(v0, v1);
          *(__half2*)(Cb16 + (size_t)row*D_ + (col & 1023)) = hv;
        } else if (OUT16){
          __half2 hv = __floats2half2_rn(v0, v1);
          *(__half2*)((__half*)Cv + (size_t)row*N + col) = hv;
        } else {
          *(float2*)((float*)Cv + (size_t)row*N + col) = make_float2(v0, v1);
        }
      }
    }
  }
}

// ---------------- fused flash attention: 128 thr, 64-q tile, clamp-aware ---
#define FST 72
#define QTILE_B (64*FST*2)        // 9216
#define KVSTG   (2*QTILE_B)       // 18432
#define FLASH_SMEM (QTILE_B + 3*KVSTG)  // 64512
#define NKT (S_/64)               // 16
__global__ void __launch_bounds__(128) flash_attn(const __half* __restrict__ Q,
                                                  const __half* __restrict__ Km,
                                                  const __half* __restrict__ Vm,
                                                  const __half* __restrict__ P,
                                                  __half* __restrict__ O)
{
  extern __shared__ char sm[];
  const int bh = blockIdx.y, b = bh >> 4, h = bh & 15;
  const int q0 = blockIdx.x*64;
  const int tid = threadIdx.x, wid = tid >> 5, lane = tid & 31;
  const int lr = lane >> 2, lc = lane & 3;
  const size_t base = (size_t)b*S_*D_ + h*HD_;
  const uint32_t smb = (uint32_t)__cvta_generic_to_shared(sm);

  const int grow = tid >> 1, gseg = (tid & 1)*32;
  {
    const __half* qg = Q + base + (size_t)(q0 + grow)*D_ + gseg;
    uint32_t dst = smb + (grow*FST + gseg)*2;
    cp16(dst,    qg);     cp16(dst+16, qg+8);
    cp16(dst+32, qg+16);  cp16(dst+48, qg+24);
  }
  CP_COMMIT();
  auto load_kv = [&](int c, int s){
    const __half* kg = Km + base + (size_t)(c*64 + grow)*D_ + gseg;
    const __half* vg = Vm + base + (size_t)(c*64 + grow)*D_ + gseg;
    uint32_t kd = smb + QTILE_B + s*KVSTG + (grow*FST + gseg)*2;
    uint32_t vd = kd + QTILE_B;
    cp16(kd,    kg);     cp16(kd+16, kg+8);
    cp16(kd+32, kg+16);  cp16(kd+48, kg+24);
    cp16(vd,    vg);     cp16(vd+16, vg+8);
    cp16(vd+32, vg+16);  cp16(vd+48, vg+24);
  };
  load_kv(0,0); CP_COMMIT();
  load_kv(1,1); CP_COMMIT();

  CP_WAIT2();
  __syncthreads();

  uint32_t a_q[4][4];
  {
    const uint32_t a_lm = smb + (((wid*16 + (lane & 15))*FST) + ((lane >> 4)*8))*2;
    const __half2 sc8 = __half2half2(__float2half(0.125f));
    #pragma unroll
    for (int ks=0; ks<4; ks++){
      ldsm4(a_q[ks][0], a_q[ks][1], a_q[ks][2], a_q[ks][3], a_lm + (ks*16)*2);
      #pragma unroll
      for (int r=0;r<4;r++){
        __half2 hv = *reinterpret_cast<__half2*>(&a_q[ks][r]);
        hv = __hmul2(hv, sc8);
        a_q[ks][r] = *reinterpret_cast<uint32_t*>(&hv);
      }
    }
  }

  const int qrow0 = q0 + wid*16 + lr;
  const __half* prow0 = P + ((size_t)(b*S_ + qrow0)*H_ + h)*NRELP + R_;
  const __half* prow1 = prow0 + (size_t)8*H_*NRELP;

  float m0 = -1e30f, m1 = -1e30f, l0 = 0.f, l1 = 0.f;
  float acc_o[8][4];
  #pragma unroll
  for (int j=0;j<8;j++)
    #pragma unroll
    for (int t=0;t<4;t++) acc_o[j][t] = 0.f;

  for (int kt = 0; kt < NKT; kt++){
    const int s = kt - (kt/3)*3;
    CP_WAIT1();
    __syncthreads();
    const uint32_t kbase = smb + QTILE_B + s*KVSTG;
    const uint32_t vbase = kbase + QTILE_B;

    float accs[8][4];
    #pragma unroll
    for (int j=0;j<8;j++)
      #pragma unroll
      for (int t=0;t<4;t++) accs[j][t] = 0.f;

    const uint32_t bk_lm = kbase
        + ((((lane & 7) + ((lane >> 4)&1)*8)*FST) + (((lane >> 3)&1)*8))*2;
    #pragma unroll
    for (int ks=0; ks<4; ks++){
      uint32_t bfr[8][2];
      #pragma unroll
      for (int np=0; np<4; np++){
        uint32_t r0,r1,r2,r3;
        ldsm4(r0,r1,r2,r3, bk_lm + (np*16*FST + ks*16)*2);
        bfr[np*2+0][0]=r0; bfr[np*2+0][1]=r1;
        bfr[np*2+1][0]=r2; bfr[np*2+1][1]=r3;
      }
      #pragma unroll
      for (int nf=0; nf<8; nf++)
        mma_f16(accs[nf], a_q[ks], bfr[nf]);
    }

    const int dmin = kt*64 - (q0 + 63);
    const int dmax = kt*64 + 63 - q0;
    if (dmin >= R_ || dmax <= -R_){
      const int off = (dmin >= R_) ? R_ : -R_;
      const float b0 = __half2float(__ldg(prow0 + off));
      const float b1 = __half2float(__ldg(prow1 + off));
      #pragma unroll
      for (int nf=0; nf<8; nf++){
        accs[nf][0] += b0; accs[nf][1] += b0;
        accs[nf][2] += b1; accs[nf][3] += b1;
      }
    } else {
      const int cq0 = kt*64 + 2*lc - qrow0;
      #pragma unroll
      for (int nf=0; nf<8; nf++){
        int c0 = cq0 + nf*8;
        int i00 = c0;     i00 = i00 < -R_ ? -R_ : (i00 > R_ ? R_ : i00);
        int i01 = c0 + 1; i01 = i01 < -R_ ? -R_ : (i01 > R_ ? R_ : i01);
        int i10 = c0 - 8; i10 = i10 < -R_ ? -R_ : (i10 > R_ ? R_ : i10);
        int i11 = c0 - 7; i11 = i11 < -R_ ? -R_ : (i11 > R_ ? R_ : i11);
        accs[nf][0] += __half2float(__ldg(prow0 + i00));
        accs[nf][1] += __half2float(__ldg(prow0 + i01));
        accs[nf][2] += __half2float(__ldg(prow1 + i10));
        accs[nf][3] += __half2float(__ldg(prow1 + i11));
      }
    }

    float mx0 = -1e30f, mx1 = -1e30f;
    #pragma unroll
    for (int nf=0; nf<8; nf++){
      mx0 = fmaxf(mx0, fmaxf(accs[nf][0], accs[nf][1]));
      mx1 = fmaxf(mx1, fmaxf(accs[nf][2], accs[nf][3]));
    }
    mx0 = fmaxf(mx0, __shfl_xor_sync(0xffffffffu, mx0, 1));
    mx0 = fmaxf(mx0, __shfl_xor_sync(0xffffffffu, mx0, 2));
    mx1 = fmaxf(mx1, __shfl_xor_sync(0xffffffffu, mx1, 1));
    mx1 = fmaxf(mx1, __shfl_xor_sync(0xffffffffu, mx1, 2));
    const float mn0 = fmaxf(m0, mx0), mn1 = fmaxf(m1, mx1);
    const float cr0 = __expf(m0 - mn0), cr1 = __expf(m1 - mn1);
    m0 = mn0; m1 = mn1;

    float rs0 = 0.f, rs1 = 0.f;
    uint32_t a_p[4][4];
    #pragma unroll
    for (int kf=0; kf<4; kf++){
      float p00 = __expf(accs[2*kf  ][0] - m0);
      float p01 = __expf(accs[2*kf  ][1] - m0);
      float p10 = __expf(accs[2*kf  ][2] - m1);
      float p11 = __expf(accs[2*kf  ][3] - m1);
      float q00 = __expf(accs[2*kf+1][0] - m0);
      float q01 = __expf(accs[2*kf+1][1] - m0);
      float q10 = __expf(accs[2*kf+1][2] - m1);
      float q11 = __expf(accs[2*kf+1][3] - m1);
      rs0 += p00 + p01 + q00 + q01;
      rs1 += p10 + p11 + q10 + q11;
      __half2 hv;
      hv = __floats2half2_rn(p00, p01); a_p[kf][0] = *reinterpret_cast<uint32_t*>(&hv);
      hv = __floats2half2_rn(p10, p11); a_p[kf][1] = *reinterpret_cast<uint32_t*>(&hv);
      hv = __floats2half2_rn(q00, q01); a_p[kf][2] = *reinterpret_cast<uint32_t*>(&hv);
      hv = __floats2half2_rn(q10, q11); a_p[kf][3] = *reinterpret_cast<uint32_t*>(&hv);
    }
    rs0 += __shfl_xor_sync(0xffffffffu, rs0, 1);
    rs0 += __shfl_xor_sync(0xffffffffu, rs0, 2);
    rs1 += __shfl_xor_sync(0xffffffffu, rs1, 1);
    rs1 += __shfl_xor_sync(0xffffffffu, rs1, 2);
    l0 = l0*cr0 + rs0;
    l1 = l1*cr1 + rs1;
    #pragma unroll
    for (int nf=0; nf<8; nf++){
      acc_o[nf][0] *= cr0; acc_o[nf][1] *= cr0;
      acc_o[nf][2] *= cr1; acc_o[nf][3] *= cr1;
    }

    const uint32_t bv_lm = vbase
        + ((((lane & 7) + ((lane >> 3)&1)*8)*FST) + (((lane >> 4)&1)*8))*2;
    #pragma unroll
    for (int kf=0; kf<4; kf++){
      uint32_t bfr[8][2];
      #pragma unroll
      for (int np=0; np<4; np++){
        uint32_t r0,r1,r2,r3;
        ldsm4t(r0,r1,r2,r3, bv_lm + (kf*16*FST + np*16)*2);
        bfr[np*2+0][0]=r0; bfr[np*2+0][1]=r1;
        bfr[np*2+1][0]=r2; bfr[np*2+1][1]=r3;
      }
      #pragma unroll
      for (int nf=0; nf<8; nf++)
        mma_f16(acc_o[nf], a_p[kf], bfr[nf]);
    }

    if (kt + 2 < NKT) load_kv(kt+2, (kt+2) - ((kt+2)/3)*3);
    CP_COMMIT();
    __syncthreads();
  }

  const float inv0 = 1.f/l0, inv1 = 1.f/l1;
  __half* orow0 = O + base + (size_t)qrow0*D_;
  __half* orow1 = orow0 + 8*D_;
  #pragma unroll
  for (int nf=0; nf<8; nf++){
    const int col = nf*8 + 2*lc;
    *(__half2*)(orow0 + col) = __floats2half2_rn(acc_o[nf][0]*inv0, acc_o[nf][1]*inv0);
    *(__half2*)(orow1 + col) = __floats2half2_rn(acc_o[nf][2]*inv1, acc_o[nf][3]*inv1);
  }
}

// ---------------- fused preprocessing: transposes + bias concat + rel cvt --
// blocks [0,12288): weight transposes; [12288,12384): rel convert;
// [12384,12396): bias concat.
__global__ void __launch_bounds__(256) prep_all(const float* __restrict__ wq,
                                                const float* __restrict__ wk,
                                                const float* __restrict__ wv,
                                                const float* __restrict__ wo,
                                                const float* __restrict__ w1,
                                                const float* __restrict__ w2,
                                                const float* __restrict__ rel,
                                                const float* __restrict__ bq,
                                                const float* __restrict__ bk,
                                                const float* __restrict__ bv,
                                                __half* __restrict__ wqkvT,
                                                __half* __restrict__ woT,
                                                __half* __restrict__ w1T,
                                                __half* __restrict__ w2T,
                                                __half* __restrict__ rel16,
                                                float* __restrict__ bqkv)
{
  const int tb = blockIdx.x;
  if (tb >= 12288){
    if (tb < 12384){
      int i = (tb - 12288)*256 + threadIdx.x;
      if (i < NRELP*HD_){
        int r = i >> 6;
        float v = (r < NREL) ? rel[i]*0.125f : 0.f;
        rel16[i] = __float2half_rn(v);
      }
    } else {
      int i = (tb - 12384)*256 + threadIdx.x;
      if (i < D_)            bqkv[i] = bq[i];
      else if (i < 2*D_)     bqkv[i] = bk[i - D_];
      else if (i < 3*D_)     bqkv[i] = bv[i - 2*D_];
    }
    return;
  }
  __shared__ float t[32][33];
  const float* W; __half* Wt; int Kd, Nd, lt;
  if      (tb <  1024){ W=wq; Wt=wqkvT;            Kd=D_;   Nd=D_;   lt=tb; }
  else if (tb <  2048){ W=wk; Wt=wqkvT +   D_*D_;  Kd=D_;   Nd=D_;   lt=tb-1024; }
  else if (tb <  3072){ W=wv; Wt=wqkvT + 2*D_*D_;  Kd=D_;   Nd=D_;   lt=tb-2048; }
  else if (tb <  4096){ W=wo; Wt=woT;              Kd=D_;   Nd=D_;   lt=tb-3072; }
  else if (tb <  8192){ W=w1; Wt=w1T;              Kd=D_;   Nd=4*D_; lt=tb-4096; }
  else                { W=w2; Wt=w2T;              Kd=4*D_; Nd=D_;   lt=tb-8192; }
  const int ntx = Nd >> 5;
  const int bx = lt % ntx, by = lt / ntx;
  const int tx = threadIdx.x & 31, ty = threadIdx.x >> 5;

  int n = bx*32 + tx;
  int k = by*32 + ty;
  #pragma unroll
  for (int i=0;i<32;i+=8)
    t[ty+i][tx] = W[(size_t)(k+i)*Nd + n];
  __syncthreads();
  int n2 = bx*32 + ty;
  int k2 = by*32 + tx;
  #pragma unroll
  for (int i=0;i<32;i+=8)
    Wt[(size_t)(n2+i)*Kd + k2] = __float2half_rn(t[tx][ty+i]);
}

// ---------------- LayerNorm: warp-per-row ----------------
__global__ void __launch_bounds__(256) ln_kernel_w(const float* __restrict__ x,
                                                   const float* __restrict__ g,
                                                   const float* __restrict__ bta,
                                                   __half* __restrict__ y)
{
  const int wid = threadIdx.x >> 5, lane = threadIdx.x & 31;
  const int row = blockIdx.x*8 + wid;
  const float* xr = x + (size_t)row*D_;
  float4 v[8];
  float s = 0.f, ss = 0.f;
  #pragma unroll
  for (int i=0;i<8;i++){
    v[i] = *(const float4*)(xr + (lane + i*32)*4);
    s  += v[i].x + v[i].y + v[i].z + v[i].w;
    ss += v[i].x*v[i].x + v[i].y*v[i].y + v[i].z*v[i].z + v[i].w*v[i].w;
  }
  s = warp_sum(s); ss = warp_sum(ss);
  const float mu = s*(1.f/(float)D_);
  const float rs = rsqrtf(ss*(1.f/(float)D_) - mu*mu + EPSLN);
  #pragma unroll
  for (int i=0;i<8;i++){
    const int c = (lane + i*32)*4;
    float4 gv = *(const float4*)(g   + c);
    float4 bv = *(const float4*)(bta + c);
    __half2 h0 = __floats2half2_rn((v[i].x-mu)*rs*gv.x + bv.x, (v[i].y-mu)*rs*gv.y + bv.y);
    __half2 h1 = __floats2half2_rn((v[i].z-mu)*rs*gv.z + bv.z, (v[i].w-mu)*rs*gv.w + bv.w);
    uint2 pk; pk.x = *(uint32_t*)&h0; pk.y = *(uint32_t*)&h1;
    *(uint2*)(y + (size_t)row*D_ + c) = pk;
  }
}

// ---------------- launcher ----------------
extern "C" void kernel_launch(void* const* d_in, const int* in_sizes, int n_in,
                              void* d_out, int out_size)
{
  const float* x    = (const float*)d_in[0];
  const float* wq   = (const float*)d_in[1];
  const float* bq   = (const float*)d_in[2];
  const float* wk   = (const float*)d_in[3];
  const float* bk   = (const float*)d_in[4];
  const float* wv   = (const float*)d_in[5];
  const float* bv   = (const float*)d_in[6];
  const float* wo   = (const float*)d_in[7];
  const float* bo   = (const float*)d_in[8];
  const float* rel  = (const float*)d_in[9];
  const float* ln1g = (const float*)d_in[10];
  const float* ln1b = (const float*)d_in[11];
  const float* ln2g = (const float*)d_in[12];
  const float* ln2b = (const float*)d_in[13];
  const float* w1   = (const float*)d_in[14];
  const float* b1   = (const float*)d_in[15];
  const float* w2   = (const float*)d_in[16];
  const float* b2   = (const float*)d_in[17];
  float* out = (float*)d_out;

  __half *h16_, *qkv16_, *o16_, *ff16_, *rel16_, *p16_;
  __half *wqkvT_, *woT_, *w1T_, *w2T_;
  float *x2_, *bqkv_, *zerob_;
  cudaGetSymbolAddress((void**)&h16_,  g_h16);
  cudaGetSymbolAddress((void**)&qkv16_,g_qkv16);
  cudaGetSymbolAddress((void**)&o16_,  g_o16);
  cudaGetSymbolAddress((void**)&ff16_, g_ff16);
  cudaGetSymbolAddress((void**)&rel16_,g_rel16);
  cudaGetSymbolAddress((void**)&p16_,  g_p16);
  cudaGetSymbolAddress((void**)&x2_,   g_x2);
  cudaGetSymbolAddress((void**)&wqkvT_,g_wqkvT);
  cudaGetSymbolAddress((void**)&bqkv_, g_bqkv);
  cudaGetSymbolAddress((void**)&zerob_,g_zerob);
  cudaGetSymbolAddress((void**)&woT_,  g_woT);
  cudaGetSymbolAddress((void**)&w1T_,  g_w1T);
  cudaGetSymbolAddress((void**)&w2T_,  g_w2T);

  __half* q16_ = qkv16_;
  __half* k16_ = qkv16_ + (size_t)BS_*D_;
  __half* v16_ = qkv16_ + (size_t)2*BS_*D_;

  static bool init_done = false;
  if (!init_done){
    cudaFuncSetAttribute(hgemm<EPI_BIAS,1,1>,       cudaFuncAttributeMaxDynamicSharedMemorySize, GEMM_SMEM);
    cudaFuncSetAttribute(hgemm<EPI_BIAS,1,0>,       cudaFuncAttributeMaxDynamicSharedMemorySize, GEMM_SMEM);
    cudaFuncSetAttribute(hgemm<EPI_BIAS_RESID,0,0>, cudaFuncAttributeMaxDynamicSharedMemorySize, GEMM_SMEM);
    cudaFuncSetAttribute(hgemm<EPI_BIAS_GELU,1,0>,  cudaFuncAttributeMaxDynamicSharedMemorySize, GEMM_SMEM);
    cudaFuncSetAttribute(flash_attn, cudaFuncAttributeMaxDynamicSharedMemorySize, FLASH_SMEM);
    init_done = true;
  }

  // 0. fused preprocessing (transposes + rel convert + bias concat)
  prep_all<<<12396, 256>>>(wq, wk, wv, wo, w1, w2, rel, bq, bk, bv,
                           wqkvT_, woT_, w1T_, w2T_, rel16_, bqkv_);

  // 1. LN1 -> fp16
  ln_kernel_w<<<BS_/8, 256>>>(x, ln1g, ln1b, h16_);
  // 2. merged QKV projection
  hgemm<EPI_BIAS,1,1><<<dim3(24,32), 256, GEMM_SMEM>>>(h16_, wqkvT_, bqkv_, nullptr, qkv16_, BS_, 3*D_, D_);
  // 3. rel projection as GEMM -> fp16 P
  hgemm<EPI_BIAS,1,0><<<dim3(3,512), 256, GEMM_SMEM>>>(q16_, rel16_, zerob_, nullptr, p16_, BS_*H_, NRELP, HD_);
  // 4. fused flash attention (clamp-aware bias) -> o16
  flash_attn<<<dim3(16, Bb_*H_), 128, FLASH_SMEM>>>(q16_, k16_, v16_, p16_, o16_);
  // 5. output projection + residual (fp32 out)
  hgemm<EPI_BIAS_RESID,0,0><<<dim3(8,32), 256, GEMM_SMEM>>>(o16_, woT_, bo, x, x2_, BS_, D_, D_);
  // 6. LN2 -> fp16
  ln_kernel_w<<<BS_/8, 256>>>(x2_, ln2g, ln2b, h16_);
  // 7. FFN1 + exact GELU (fp16 out)
  hgemm<EPI_BIAS_GELU,1,0><<<dim3(32,32), 256, GEMM_SMEM>>>(h16_, w1T_, b1, nullptr, ff16_, BS_, 4*D_, D_);
  // 8. FFN2 + residual -> out (fp32)
  hgemm<EPI_BIAS_RESID,0,0><<<dim3(8,32), 256, GEMM_SMEM>>>(ff16_, w2T_, b2, x2_, out, BS_, D_, 4*D_);
}

// round 16
// speedup vs baseline: 1.3315x; 1.0006x over previous
#include <cuda_runtime.h>
#include <cuda_fp16.h>
#include <math.h>
#include <stdint.h>

#define Bb_ 4
#define S_ 1024
#define D_ 1024
#define H_ 16
#define HD_ 64
#define R_ 128
#define NREL 257
#define NRELP 384
#define BS_ (Bb_*S_)   // 4096
#define EPSLN 1e-5f

// -------- device scratch --------
__device__ __half g_h16[BS_*D_];
__device__ __half g_qkv16[(size_t)3*BS_*D_];
__device__ __half g_o16[BS_*D_];
__device__ __half g_ff16[(size_t)BS_*4*D_];
__device__ __half g_rel16[NRELP*HD_];
__device__ __half g_p16[(size_t)BS_*H_*NRELP];    // fp16 P, stride 384
__device__ float  g_x2[BS_*D_];
__device__ __half g_wqkvT[(size_t)3*D_*D_];
__device__ float  g_bqkv[3*D_];
__device__ __half g_woT[D_*D_];
__device__ __half g_w1T[(size_t)D_*4*D_];
__device__ __half g_w2T[(size_t)4*D_*D_];

// ---------------- helpers ----------------
__device__ __forceinline__ float warp_sum(float v){
  #pragma unroll
  for (int o=16;o>0;o>>=1) v += __shfl_xor_sync(0xffffffffu, v, o);
  return v;
}
__device__ __forceinline__ void mma_f16(float* d, const uint32_t* a, const uint32_t* b){
  asm volatile("mma.sync.aligned.m16n8k16.row.col.f32.f16.f16.f32 "
    "{%0,%1,%2,%3}, {%4,%5,%6,%7}, {%8,%9}, {%0,%1,%2,%3};"
    : "+f"(d[0]),"+f"(d[1]),"+f"(d[2]),"+f"(d[3])
    : "r"(a[0]),"r"(a[1]),"r"(a[2]),"r"(a[3]), "r"(b[0]),"r"(b[1]));
}
__device__ __forceinline__ void ldsm4(uint32_t& r0, uint32_t& r1, uint32_t& r2, uint32_t& r3,
                                      uint32_t addr){
  asm volatile("ldmatrix.sync.aligned.m8n8.x4.shared.b16 {%0,%1,%2,%3}, [%4];"
    : "=r"(r0),"=r"(r1),"=r"(r2),"=r"(r3) : "r"(addr));
}
__device__ __forceinline__ void ldsm4t(uint32_t& r0, uint32_t& r1, uint32_t& r2, uint32_t& r3,
                                       uint32_t addr){
  asm volatile("ldmatrix.sync.aligned.m8n8.x4.trans.shared.b16 {%0,%1,%2,%3}, [%4];"
    : "=r"(r0),"=r"(r1),"=r"(r2),"=r"(r3) : "r"(addr));
}
__device__ __forceinline__ void cp16(uint32_t dst, const void* src){
  asm volatile("cp.async.cg.shared.global [%0], [%1], 16;" :: "r"(dst), "l"(src));
}
#define CP_COMMIT() asm volatile("cp.async.commit_group;" ::: "memory")
#define CP_WAIT1()  asm volatile("cp.async.wait_group 1;" ::: "memory")
#define CP_WAIT0()  asm volatile("cp.async.wait_group 0;" ::: "memory")
#define CP_WAIT2()  asm volatile("cp.async.wait_group 2;" ::: "memory")

#define EPI_BIAS        0
#define EPI_BIAS_RESID  1
#define EPI_BIAS_GELU   2
#define HST 40
#define HBYTES (128*HST*2)          // 10240
#define GEMM_SMEM (6*HBYTES)        // 61440 -> 2 CTAs/SM

// ---------------- fp16 mma GEMM: 128x128x32, 8 warps, 3-stage -------------
template<int EPI, int OUT16, int SPLIT>
__global__ void __launch_bounds__(256) hgemm(const __half* __restrict__ A,
                                             const __half* __restrict__ Bt,
                                             const float* __restrict__ bias,
                                             const float* __restrict__ resid,
                                             void* __restrict__ Cv,
                                             int M, int N, int K)
{
  extern __shared__ char sm[];
  __half* Asm = (__half*)sm;
  __half* Bsm = (__half*)(sm + 3*HBYTES);
  const int tid = threadIdx.x;
  const int wid = tid >> 5, lane = tid & 31;
  const int warp_m = wid >> 1, warp_n = wid & 1;
  const int m0 = blockIdx.y*128, n0 = blockIdx.x*128;
  const int lr = lane >> 2, lc = lane & 3;
  const int grow = tid >> 1, gseg = (tid & 1)*16;

  const __half* Ag = A  + (size_t)(m0 + grow)*K + gseg;
  const __half* Bg = Bt + (size_t)(n0 + grow)*K + gseg;
  const uint32_t a_s = (uint32_t)__cvta_generic_to_shared(Asm) + (grow*HST + gseg)*2;
  const uint32_t b_s = (uint32_t)__cvta_generic_to_shared(Bsm) + (grow*HST + gseg)*2;

  const uint32_t a_lm = (uint32_t)__cvta_generic_to_shared(Asm)
      + (((warp_m*32 + (lane & 15))*HST) + ((lane >> 4)*8))*2;
  const uint32_t b_lm = (uint32_t)__cvta_generic_to_shared(Bsm)
      + (((warp_n*64 + (lane & 7) + ((lane >> 4)&1)*8)*HST) + (((lane >> 3)&1)*8))*2;

  float acc[2][8][4];
  #pragma unroll
  for (int i=0;i<2;i++)
    #pragma unroll
    for (int j=0;j<8;j++)
      #pragma unroll
      for (int t=0;t<4;t++) acc[i][j][t]=0.f;

  const int NC = K >> 5;
  auto load = [&](int c, int s){
    const __half* ga = Ag + c*32;
    const __half* gb = Bg + c*32;
    const uint32_t da = a_s + s*HBYTES;
    const uint32_t db = b_s + s*HBYTES;
    cp16(da,      ga);
    cp16(da + 16, ga + 8);
    cp16(db,      gb);
    cp16(db + 16, gb + 8);
  };

  load(0,0); CP_COMMIT();
  if (NC > 1) load(1,1);
  CP_COMMIT();

  for (int c = 0; c < NC; c++){
    const int s = c - (c/3)*3;
    if (c + 1 < NC) CP_WAIT1(); else CP_WAIT0();
    __syncthreads();
    const uint32_t abase = a_lm + s*HBYTES;
    const uint32_t bbase = b_lm + s*HBYTES;
    #pragma unroll
    for (int ks=0; ks<2; ks++){
      uint32_t a[2][4], b[8][2];
      #pragma unroll
      for (int mf=0; mf<2; mf++)
        ldsm4(a[mf][0], a[mf][1], a[mf][2], a[mf][3],
              abase + (mf*16*HST + ks*16)*2);
      #pragma unroll
      for (int np=0; np<4; np++){
        uint32_t r0,r1,r2,r3;
        ldsm4(r0,r1,r2,r3, bbase + (np*16*HST + ks*16)*2);
        b[np*2+0][0]=r0; b[np*2+0][1]=r1;
        b[np*2+1][0]=r2; b[np*2+1][1]=r3;
      }
      #pragma unroll
      for (int mf=0; mf<2; mf++)
        #pragma unroll
        for (int nf=0; nf<8; nf++)
          mma_f16(acc[mf][nf], a[mf], b[nf]);
    }
    if (c + 2 < NC) load(c+2, (c+2) - ((c+2)/3)*3);
    CP_COMMIT();
    __syncthreads();
  }

  __half* Cb16 = nullptr;
  if (SPLIT) Cb16 = (__half*)Cv + (size_t)(n0 >> 10)*BS_*D_;
  #pragma unroll
  for (int mf=0; mf<2; mf++){
    #pragma unroll
    for (int half=0; half<2; half++){
      const int row = m0 + warp_m*32 + mf*16 + lr + half*8;
      const float* rrow = (EPI == EPI_BIAS_RESID) ? (resid + (size_t)row*N) : nullptr;
      #pragma unroll
      for (int nf=0; nf<8; nf++){
        const int col = n0 + warp_n*64 + nf*8 + 2*lc;
        float v0 = acc[mf][nf][half*2 + 0] + bias[col];
        float v1 = acc[mf][nf][half*2 + 1] + bias[col+1];
        if (EPI == EPI_BIAS_RESID){ v0 += rrow[col]; v1 += rrow[col+1]; }
        if (EPI == EPI_BIAS_GELU){
          v0 = 0.5f*v0*(1.0f + erff(v0*0.70710678118654752f));
          v1 = 0.5f*v1*(1.0f + erff(v1*0.70710678118654752f));
        }
        if (SPLIT){
          __half2 hv = __floats2half2_rn(v0, v1);
          *(__half2*)(Cb16 + (size_t)row*D_ + (col & 1023)) = hv;
        } else if (OUT16){
          __half2 hv = __floats2half2_rn(v0, v1);
          *(__half2*)((__half*)Cv + (size_t)row*N + col) = hv;
        } else {
          *(float2*)((float*)Cv + (size_t)row*N + col) = make_float2(v0, v1);
        }
      }
    }
  }
}

// ---------------- dedicated rel projection: P = Qview[65536,64] @ rel16^T --
// grid (3, 128): n0 = bx*128; each CTA does 4 m-tiles of 128 rows,
// B tile (rel16 rows n0..n0+127) resident in smem, A double-buffered.
#define RST 72
#define RTILE_B (128*RST*2)            // 18432
#define RELP_SMEM (3*RTILE_B)          // 55296
__global__ void __launch_bounds__(256) relproj_mma(const __half* __restrict__ Q,
                                                   const __half* __restrict__ Rel,
                                                   __half* __restrict__ P)
{
  extern __shared__ char sm[];
  const uint32_t smb = (uint32_t)__cvta_generic_to_shared(sm);
  const int tid = threadIdx.x;
  const int wid = tid >> 5, lane = tid & 31;
  const int warp_m = wid >> 1, warp_n = wid & 1;
  const int n0 = blockIdx.x*128;
  const int mt0 = blockIdx.y*4;        // first m-tile index
  const int lr = lane >> 2, lc = lane & 3;

  const int grow = tid >> 1, gseg = (tid & 1)*32;   // 2 thr/row, 32 halves
  // B load (once): rel16 row stride 64 halves
  {
    const __half* bg = Rel + (size_t)(n0 + grow)*HD_ + gseg;
    uint32_t dst = smb + (grow*RST + gseg)*2;
    cp16(dst,    bg);     cp16(dst+16, bg+8);
    cp16(dst+32, bg+16);  cp16(dst+48, bg+24);
  }
  auto loadA = [&](int it, int s){
    const __half* ag = Q + (size_t)((mt0 + it)*128 + grow)*HD_ + gseg;
    uint32_t dst = smb + RTILE_B + s*RTILE_B + (grow*RST + gseg)*2;
    cp16(dst,    ag);     cp16(dst+16, ag+8);
    cp16(dst+32, ag+16);  cp16(dst+48, ag+24);
  };
  loadA(0, 0); CP_COMMIT();     // group: B + A0
  loadA(1, 1); CP_COMMIT();     // group: A1

  const uint32_t b_lm = smb
      + (((warp_n*64 + (lane & 7) + ((lane >> 4)&1)*8)*RST) + (((lane >> 3)&1)*8))*2;
  const uint32_t a_lm0 = smb + RTILE_B
      + (((warp_m*32 + (lane & 15))*RST) + ((lane >> 4)*8))*2;

  for (int it = 0; it < 4; it++){
    if (it + 2 < 4) CP_WAIT1(); else CP_WAIT0();
    __syncthreads();
    const uint32_t abase = a_lm0 + (it & 1)*RTILE_B;

    float acc[2][8][4];
    #pragma unroll
    for (int i=0;i<2;i++)
      #pragma unroll
      for (int j=0;j<8;j++)
        #pragma unroll
        for (int t=0;t<4;t++) acc[i][j][t]=0.f;

    #pragma unroll
    for (int ks=0; ks<4; ks++){
      uint32_t a[2][4], b[8][2];
      #pragma unroll
      for (int mf=0; mf<2; mf++)
        ldsm4(a[mf][0], a[mf][1], a[mf][2], a[mf][3],
              abase + (mf*16*RST + ks*16)*2);
      #pragma unroll
      for (int np=0; np<4; np++){
        uint32_t r0,r1,r2,r3;
        ldsm4(r0,r1,r2,r3, b_lm + (np*16*RST + ks*16)*2);
        b[np*2+0][0]=r0; b[np*2+0][1]=r1;
        b[np*2+1][0]=r2; b[np*2+1][1]=r3;
      }
      #pragma unroll
      for (int mf=0; mf<2; mf++)
        #pragma unroll
        for (int nf=0; nf<8; nf++)
          mma_f16(acc[mf][nf], a[mf], b[nf]);
    }
    __syncthreads();                       // all warps done reading this A buf
    if (it + 2 < 4){ loadA(it + 2, it & 1); CP_COMMIT(); }

    const int m0 = (mt0 + it)*128;
    #pragma unroll
    for (int mf=0; mf<2; mf++){
      #pragma unroll
      for (int half=0; half<2; half++){
        const int row = m0 + warp_m*32 + mf*16 + lr + half*8;
        __half* prow = P + (size_t)row*NRELP;
        #pragma unroll
        for (int nf=0; nf<8; nf++){
          const int col = n0 + warp_n*64 + nf*8 + 2*lc;
          __half2 hv = __floats2half2_rn(acc[mf][nf][half*2 + 0],
                                         acc[mf][nf][half*2 + 1]);
          *(__half2*)(prow + col) = hv;
        }
      }
    }
  }
}

// ---------------- fused flash attention: 128 thr, 64-q tile, clamp-aware ---
#define FST 72
#define QTILE_B (64*FST*2)        // 9216
#define KVSTG   (2*QTILE_B)       // 18432
#define FLASH_SMEM (QTILE_B + 3*KVSTG)  // 64512
#define NKT (S_/64)               // 16
__global__ void __launch_bounds__(128) flash_attn(const __half* __restrict__ Q,
                                                  const __half* __restrict__ Km,
                                                  const __half* __restrict__ Vm,
                                                  const __half* __restrict__ P,
                                                  __half* __restrict__ O)
{
  extern __shared__ char sm[];
  const int bh = blockIdx.y, b = bh >> 4, h = bh & 15;
  const int q0 = blockIdx.x*64;
  const int tid = threadIdx.x, wid = tid >> 5, lane = tid & 31;
  const int lr = lane >> 2, lc = lane & 3;
  const size_t base = (size_t)b*S_*D_ + h*HD_;
  const uint32_t smb = (uint32_t)__cvta_generic_to_shared(sm);

  const int grow = tid >> 1, gseg = (tid & 1)*32;
  {
    const __half* qg = Q + base + (size_t)(q0 + grow)*D_ + gseg;
    uint32_t dst = smb + (grow*FST + gseg)*2;
    cp16(dst,    qg);     cp16(dst+16, qg+8);
    cp16(dst+32, qg+16);  cp16(dst+48, qg+24);
  }
  CP_COMMIT();
  auto load_kv = [&](int c, int s){
    const __half* kg = Km + base + (size_t)(c*64 + grow)*D_ + gseg;
    const __half* vg = Vm + base + (size_t)(c*64 + grow)*D_ + gseg;
    uint32_t kd = smb + QTILE_B + s*KVSTG + (grow*FST + gseg)*2;
    uint32_t vd = kd + QTILE_B;
    cp16(kd,    kg);     cp16(kd+16, kg+8);
    cp16(kd+32, kg+16);  cp16(kd+48, kg+24);
    cp16(vd,    vg);     cp16(vd+16, vg+8);
    cp16(vd+32, vg+16);  cp16(vd+48, vg+24);
  };
  load_kv(0,0); CP_COMMIT();
  load_kv(1,1); CP_COMMIT();

  CP_WAIT2();
  __syncthreads();

  uint32_t a_q[4][4];
  {
    const uint32_t a_lm = smb + (((wid*16 + (lane & 15))*FST) + ((lane >> 4)*8))*2;
    const __half2 sc8 = __half2half2(__float2half(0.125f));
    #pragma unroll
    for (int ks=0; ks<4; ks++){
      ldsm4(a_q[ks][0], a_q[ks][1], a_q[ks][2], a_q[ks][3], a_lm + (ks*16)*2);
      #pragma unroll
      for (int r=0;r<4;r++){
        __half2 hv = *reinterpret_cast<__half2*>(&a_q[ks][r]);
        hv = __hmul2(hv, sc8);
        a_q[ks][r] = *reinterpret_cast<uint32_t*>(&hv);
      }
    }
  }

  const int qrow0 = q0 + wid*16 + lr;
  const __half* prow0 = P + ((size_t)(b*S_ + qrow0)*H_ + h)*NRELP + R_;
  const __half* prow1 = prow0 + (size_t)8*H_*NRELP;

  float m0 = -1e30f, m1 = -1e30f, l0 = 0.f, l1 = 0.f;
  float acc_o[8][4];
  #pragma unroll
  for (int j=0;j<8;j++)
    #pragma unroll
    for (int t=0;t<4;t++) acc_o[j][t] = 0.f;

  for (int kt = 0; kt < NKT; kt++){
    const int s = kt - (kt/3)*3;
    CP_WAIT1();
    __syncthreads();
    const uint32_t kbase = smb + QTILE_B + s*KVSTG;
    const uint32_t vbase = kbase + QTILE_B;

    float accs[8][4];
    #pragma unroll
    for (int j=0;j<8;j++)
      #pragma unroll
      for (int t=0;t<4;t++) accs[j][t] = 0.f;

    const uint32_t bk_lm = kbase
        + ((((lane & 7) + ((lane >> 4)&1)*8)*FST) + (((lane >> 3)&1)*8))*2;
    #pragma unroll
    for (int ks=0; ks<4; ks++){
      uint32_t bfr[8][2];
      #pragma unroll
      for (int np=0; np<4; np++){
        uint32_t r0,r1,r2,r3;
        ldsm4(r0,r1,r2,r3, bk_lm + (np*16*FST + ks*16)*2);
        bfr[np*2+0][0]=r0; bfr[np*2+0][1]=r1;
        bfr[np*2+1][0]=r2; bfr[np*2+1][1]=r3;
      }
      #pragma unroll
      for (int nf=0; nf<8; nf++)
        mma_f16(accs[nf], a_q[ks], bfr[nf]);
    }

    const int dmin = kt*64 - (q0 + 63);
    const int dmax = kt*64 + 63 - q0;
    if (dmin >= R_ || dmax <= -R_){
      const int off = (dmin >= R_) ? R_ : -R_;
      const float b0 = __half2float(__ldg(prow0 + off));
      const float b1 = __half2float(__ldg(prow1 + off));
      #pragma unroll
      for (int nf=0; nf<8; nf++){
        accs[nf][0] += b0; accs[nf][1] += b0;
        accs[nf][2] += b1; accs[nf][3] += b1;
      }
    } else {
      const int cq0 = kt*64 + 2*lc - qrow0;
      #pragma unroll
      for (int nf=0; nf<8; nf++){
        int c0 = cq0 + nf*8;
        int i00 = c0;     i00 = i00 < -R_ ? -R_ : (i00 > R_ ? R_ : i00);
        int i01 = c0 + 1; i01 = i01 < -R_ ? -R_ : (i01 > R_ ? R_ : i01);
        int i10 = c0 - 8; i10 = i10 < -R_ ? -R_ : (i10 > R_ ? R_ : i10);
        int i11 = c0 - 7; i11 = i11 < -R_ ? -R_ : (i11 > R_ ? R_ : i11);
        accs[nf][0] += __half2float(__ldg(prow0 + i00));
        accs[nf][1] += __half2float(__ldg(prow0 + i01));
        accs[nf][2] += __half2float(__ldg(prow1 + i10));
        accs[nf][3] += __half2float(__ldg(prow1 + i11));
      }
    }

    float mx0 = -1e30f, mx1 = -1e30f;
    #pragma unroll
    for (int nf=0; nf<8; nf++){
      mx0 = fmaxf(mx0, fmaxf(accs[nf][0], accs[nf][1]));
      mx1 = fmaxf(mx1, fmaxf(accs[nf][2], accs[nf][3]));
    }
    mx0 = fmaxf(mx0, __shfl_xor_sync(0xffffffffu, mx0, 1));
    mx0 = fmaxf(mx0, __shfl_xor_sync(0xffffffffu, mx0, 2));
    mx1 = fmaxf(mx1, __shfl_xor_sync(0xffffffffu, mx1, 1));
    mx1 = fmaxf(mx1, __shfl_xor_sync(0xffffffffu, mx1, 2));
    const float mn0 = fmaxf(m0, mx0), mn1 = fmaxf(m1, mx1);
    const float cr0 = __expf(m0 - mn0), cr1 = __expf(m1 - mn1);
    m0 = mn0; m1 = mn1;

    float rs0 = 0.f, rs1 = 0.f;
    uint32_t a_p[4][4];
    #pragma unroll
    for (int kf=0; kf<4; kf++){
      float p00 = __expf(accs[2*kf  ][0] - m0);
      float p01 = __expf(accs[2*kf  ][1] - m0);
      float p10 = __expf(accs[2*kf  ][2] - m1);
      float p11 = __expf(accs[2*kf  ][3] - m1);
      float q00 = __expf(accs[2*kf+1][0] - m0);
      float q01 = __expf(accs[2*kf+1][1] - m0);
      float q10 = __expf(accs[2*kf+1][2] - m1);
      float q11 = __expf(accs[2*kf+1][3] - m1);
      rs0 += p00 + p01 + q00 + q01;
      rs1 += p10 + p11 + q10 + q11;
      __half2 hv;
      hv = __floats2half2_rn(p00, p01); a_p[kf][0] = *reinterpret_cast<uint32_t*>(&hv);
      hv = __floats2half2_rn(p10, p11); a_p[kf][1] = *reinterpret_cast<uint32_t*>(&hv);
      hv = __floats2half2_rn(q00, q01); a_p[kf][2] = *reinterpret_cast<uint32_t*>(&hv);
      hv = __floats2half2_rn(q10, q11); a_p[kf][3] = *reinterpret_cast<uint32_t*>(&hv);
    }
    rs0 += __shfl_xor_sync(0xffffffffu, rs0, 1);
    rs0 += __shfl_xor_sync(0xffffffffu, rs0, 2);
    rs1 += __shfl_xor_sync(0xffffffffu, rs1, 1);
    rs1 += __shfl_xor_sync(0xffffffffu, rs1, 2);
    l0 = l0*cr0 + rs0;
    l1 = l1*cr1 + rs1;
    #pragma unroll
    for (int nf=0; nf<8; nf++){
      acc_o[nf][0] *= cr0; acc_o[nf][1] *= cr0;
      acc_o[nf][2] *= cr1; acc_o[nf][3] *= cr1;
    }

    const uint32_t bv_lm = vbase
        + ((((lane & 7) + ((lane >> 3)&1)*8)*FST) + (((lane >> 4)&1)*8))*2;
    #pragma unroll
    for (int kf=0; kf<4; kf++){
      uint32_t bfr[8][2];
      #pragma unroll
      for (int np=0; np<4; np++){
        uint32_t r0,r1,r2,r3;
        ldsm4t(r0,r1,r2,r3, bv_lm + (kf*16*FST + np*16)*2);
        bfr[np*2+0][0]=r0; bfr[np*2+0][1]=r1;
        bfr[np*2+1][0]=r2; bfr[np*2+1][1]=r3;
      }
      #pragma unroll
      for (int nf=0; nf<8; nf++)
        mma_f16(acc_o[nf], a_p[kf], bfr[nf]);
    }

    if (kt + 2 < NKT) load_kv(kt+2, (kt+2) - ((kt+2)/3)*3);
    CP_COMMIT();
    __syncthreads();
  }

  const float inv0 = 1.f/l0, inv1 = 1.f/l1;
  __half* orow0 = O + base + (size_t)qrow0*D_;
  __half* orow1 = orow0 + 8*D_;
  #pragma unroll
  for (int nf=0; nf<8; nf++){
    const int col = nf*8 + 2*lc;
    *(__half2*)(orow0 + col) = __floats2half2_rn(acc_o[nf][0]*inv0, acc_o[nf][1]*inv0);
    *(__half2*)(orow1 + col) = __floats2half2_rn(acc_o[nf][2]*inv1, acc_o[nf][3]*inv1);
  }
}

// ---------------- fused preprocessing ----------------
__global__ void __launch_bounds__(256) prep_all(const float* __restrict__ wq,
                                                const float* __restrict__ wk,
                                                const float* __restrict__ wv,
                                                const float* __restrict__ wo,
                                                const float* __restrict__ w1,
                                                const float* __restrict__ w2,
                                                const float* __restrict__ rel,
                                                const float* __restrict__ bq,
                                                const float* __restrict__ bk,
                                                const float* __restrict__ bv,
                                                __half* __restrict__ wqkvT,
                                                __half* __restrict__ woT,
                                                __half* __restrict__ w1T,
                                                __half* __restrict__ w2T,
                                                __half* __restrict__ rel16,
                                                float* __restrict__ bqkv)
{
  const int tb = blockIdx.x;
  if (tb >= 12288){
    if (tb < 12384){
      int i = (tb - 12288)*256 + threadIdx.x;
      if (i < NRELP*HD_){
        int r = i >> 6;
        float v = (r < NREL) ? rel[i]*0.125f : 0.f;
        rel16[i] = __float2half_rn(v);
      }
    } else {
      int i = (tb - 12384)*256 + threadIdx.x;
      if (i < D_)            bqkv[i] = bq[i];
      else if (i < 2*D_)     bqkv[i] = bk[i - D_];
      else if (i < 3*D_)     bqkv[i] = bv[i - 2*D_];
    }
    return;
  }
  __shared__ float t[32][33];
  const float* W; __half* Wt; int Kd, Nd, lt;
  if      (tb <  1024){ W=wq; Wt=wqkvT;            Kd=D_;   Nd=D_;   lt=tb; }
  else if (tb <  2048){ W=wk; Wt=wqkvT +   D_*D_;  Kd=D_;   Nd=D_;   lt=tb-1024; }
  else if (tb <  3072){ W=wv; Wt=wqkvT + 2*D_*D_;  Kd=D_;   Nd=D_;   lt=tb-2048; }
  else if (tb <  4096){ W=wo; Wt=woT;              Kd=D_;   Nd=D_;   lt=tb-3072; }
  else if (tb <  8192){ W=w1; Wt=w1T;              Kd=D_;   Nd=4*D_; lt=tb-4096; }
  else                { W=w2; Wt=w2T;              Kd=4*D_; Nd=D_;   lt=tb-8192; }
  const int ntx = Nd >> 5;
  const int bx = lt % ntx, by = lt / ntx;
  const int tx = threadIdx.x & 31, ty = threadIdx.x >> 5;

  int n = bx*32 + tx;
  int k = by*32 + ty;
  #pragma unroll
  for (int i=0;i<32;i+=8)
    t[ty+i][tx] = W[(size_t)(k+i)*Nd + n];
  __syncthreads();
  int n2 = bx*32 + ty;
  int k2 = by*32 + tx;
  #pragma unroll
  for (int i=0;i<32;i+=8)
    Wt[(size_t)(n2+i)*Kd + k2] = __float2half_rn(t[tx][ty+i]);
}

// ---------------- LayerNorm: warp-per-row ----------------
__global__ void __launch_bounds__(256) ln_kernel_w(const float* __restrict__ x,
                                                   const float* __restrict__ g,
                                                   const float* __restrict__ bta,
                                                   __half* __restrict__ y)
{
  const int wid = threadIdx.x >> 5, lane = threadIdx.x & 31;
  const int row = blockIdx.x*8 + wid;
  const float* xr = x + (size_t)row*D_;
  float4 v[8];
  float s = 0.f, ss = 0.f;
  #pragma unroll
  for (int i=0;i<8;i++){
    v[i] = *(const float4*)(xr + (lane + i*32)*4);
    s  += v[i].x + v[i].y + v[i].z + v[i].w;
    ss += v[i].x*v[i].x + v[i].y*v[i].y + v[i].z*v[i].z + v[i].w*v[i].w;
  }
  s = warp_sum(s); ss = warp_sum(ss);
  const float mu = s*(1.f/(float)D_);
  const float rs = rsqrtf(ss*(1.f/(float)D_) - mu*mu + EPSLN);
  #pragma unroll
  for (int i=0;i<8;i++){
    const int c = (lane + i*32)*4;
    float4 gv = *(const float4*)(g   + c);
    float4 bv = *(const float4*)(bta + c);
    __half2 h0 = __floats2half2_rn((v[i].x-mu)*rs*gv.x + bv.x, (v[i].y-mu)*rs*gv.y + bv.y);
    __half2 h1 = __floats2half2_rn((v[i].z-mu)*rs*gv.z + bv.z, (v[i].w-mu)*rs*gv.w + bv.w);
    uint2 pk; pk.x = *(uint32_t*)&h0; pk.y = *(uint32_t*)&h1;
    *(uint2*)(y + (size_t)row*D_ + c) = pk;
  }
}

// ---------------- launcher ----------------
extern "C" void kernel_launch(void* const* d_in, const int* in_sizes, int n_in,
                              void* d_out, int out_size)
{
  const float* x    = (const float*)d_in[0];
  const float* wq   = (const float*)d_in[1];
  const float* bq   = (const float*)d_in[2];
  const float* wk   = (const float*)d_in[3];
  const float* bk   = (const float*)d_in[4];
  const float* wv   = (const float*)d_in[5];
  const float* bv   = (const float*)d_in[6];
  const float* wo   = (const float*)d_in[7];
  const float* bo   = (const float*)d_in[8];
  const float* rel  = (const float*)d_in[9];
  const float* ln1g = (const float*)d_in[10];
  const float* ln1b = (const float*)d_in[11];
  const float* ln2g = (const float*)d_in[12];
  const float* ln2b = (const float*)d_in[13];
  const float* w1   = (const float*)d_in[14];
  const float* b1   = (const float*)d_in[15];
  const float* w2   = (const float*)d_in[16];
  const float* b2   = (const float*)d_in[17];
  float* out = (float*)d_out;

  __half *h16_, *qkv16_, *o16_, *ff16_, *rel16_, *p16_;
  __half *wqkvT_, *woT_, *w1T_, *w2T_;
  float *x2_, *bqkv_;
  cudaGetSymbolAddress((void**)&h16_,  g_h16);
  cudaGetSymbolAddress((void**)&qkv16_,g_qkv16);
  cudaGetSymbolAddress((void**)&o16_,  g_o16);
  cudaGetSymbolAddress((void**)&ff16_, g_ff16);
  cudaGetSymbolAddress((void**)&rel16_,g_rel16);
  cudaGetSymbolAddress((void**)&p16_,  g_p16);
  cudaGetSymbolAddress((void**)&x2_,   g_x2);
  cudaGetSymbolAddress((void**)&wqkvT_,g_wqkvT);
  cudaGetSymbolAddress((void**)&bqkv_, g_bqkv);
  cudaGetSymbolAddress((void**)&woT_,  g_woT);
  cudaGetSymbolAddress((void**)&w1T_,  g_w1T);
  cudaGetSymbolAddress((void**)&w2T_,  g_w2T);

  __half* q16_ = qkv16_;
  __half* k16_ = qkv16_ + (size_t)BS_*D_;
  __half* v16_ = qkv16_ + (size_t)2*BS_*D_;

  static bool init_done = false;
  if (!init_done){
    cudaFuncSetAttribute(hgemm<EPI_BIAS,1,1>,       cudaFuncAttributeMaxDynamicSharedMemorySize, GEMM_SMEM);
    cudaFuncSetAttribute(hgemm<EPI_BIAS_RESID,0,0>, cudaFuncAttributeMaxDynamicSharedMemorySize, GEMM_SMEM);
    cudaFuncSetAttribute(hgemm<EPI_BIAS_GELU,1,0>,  cudaFuncAttributeMaxDynamicSharedMemorySize, GEMM_SMEM);
    cudaFuncSetAttribute(relproj_mma, cudaFuncAttributeMaxDynamicSharedMemorySize, RELP_SMEM);
    cudaFuncSetAttribute(flash_attn,  cudaFuncAttributeMaxDynamicSharedMemorySize, FLASH_SMEM);
    init_done = true;
  }

  // 0. fused preprocessing (transposes + rel convert + bias concat)
  prep_all<<<12396, 256>>>(wq, wk, wv, wo, w1, w2, rel, bq, bk, bv,
                           wqkvT_, woT_, w1T_, w2T_, rel16_, bqkv_);

  // 1. LN1 -> fp16
  ln_kernel_w<<<BS_/8, 256>>>(x, ln1g, ln1b, h16_);
  // 2. merged QKV projection
  hgemm<EPI_BIAS,1,1><<<dim3(24,32), 256, GEMM_SMEM>>>(h16_, wqkvT_, bqkv_, nullptr, qkv16_, BS_, 3*D_, D_);
  // 3. dedicated rel projection (B resident, 4 m-tiles per CTA) -> fp16 P
  relproj_mma<<<dim3(3,128), 256, RELP_SMEM>>>(q16_, rel16_, p16_);
  // 4. fused flash attention (clamp-aware bias) -> o16
  flash_attn<<<dim3(16, Bb_*H_), 128, FLASH_SMEM>>>(q16_, k16_, v16_, p16_, o16_);
  // 5. output projection + residual (fp32 out)
  hgemm<EPI_BIAS_RESID,0,0><<<dim3(8,32), 256, GEMM_SMEM>>>(o16_, woT_, bo, x, x2_, BS_, D_, D_);
  // 6. LN2 -> fp16
  ln_kernel_w<<<BS_/8, 256>>>(x2_, ln2g, ln2b, h16_);
  // 7. FFN1 + exact GELU (fp16 out)
  hgemm<EPI_BIAS_GELU,1,0><<<dim3(32,32), 256, GEMM_SMEM>>>(h16_, w1T_, b1, nullptr, ff16_, BS_, 4*D_, D_);
  // 8. FFN2 + residual -> out (fp32)
  hgemm<EPI_BIAS_RESID,0,0><<<dim3(8,32), 256, GEMM_SMEM>>>(ff16_, w2T_, b2, x2_, out, BS_, D_, 4*D_);
}